// round 1
// baseline (speedup 1.0000x reference)
#include <cuda_runtime.h>
#include <cstdint>

#define N_NODES 100000
#define N_EDGES 1600000
#define NFEAT   512
#define NHID    256
#define NCLASS  40
#define NF4     (NCLASS / 4)   // 10 float4 per feature row

#define SCAN_T  1024
#define NBLK    ((N_NODES + SCAN_T - 1) / SCAN_T)   // 98

// ---------------- scratch (static device globals; no allocation) ----------------
__device__ float g_h1[(size_t)N_NODES * NHID];     // 102.4 MB
__device__ float g_h2[(size_t)N_NODES * NHID];     // 102.4 MB
__device__ float g_h [(size_t)N_NODES * NCLASS];   // 16 MB
__device__ float g_vA[(size_t)N_NODES * NCLASS];   // 16 MB
__device__ float g_vB[(size_t)N_NODES * NCLASS];   // 16 MB
__device__ float g_dinv[N_NODES];
__device__ int   g_cnt [N_NODES];
__device__ int   g_fill[N_NODES];
__device__ int   g_rowstart[N_NODES + 1];
__device__ int   g_cols[N_EDGES];
__device__ int   g_bsum[128];

// ---------------- graph preprocessing ----------------
__global__ void zero_counts() {
    int i = blockIdx.x * blockDim.x + threadIdx.x;
    if (i < N_NODES) { g_cnt[i] = 0; g_fill[i] = 0; }
}

__global__ void count_deg(const int* __restrict__ rows) {
    int e = blockIdx.x * blockDim.x + threadIdx.x;
    if (e < N_EDGES) atomicAdd(&g_cnt[rows[e]], 1);
}

__global__ void compute_dinv() {
    int i = blockIdx.x * blockDim.x + threadIdx.x;
    if (i < N_NODES) g_dinv[i] = 1.0f / (float)(g_cnt[i] + 1);  // +1 self loop
}

// exclusive scan of g_cnt -> g_rowstart (2-level)
__global__ void scan_blocks() {
    __shared__ int s[SCAN_T];
    int t   = threadIdx.x;
    int gid = blockIdx.x * SCAN_T + t;
    int v   = (gid < N_NODES) ? g_cnt[gid] : 0;
    s[t] = v;
    __syncthreads();
    #pragma unroll
    for (int off = 1; off < SCAN_T; off <<= 1) {
        int x = (t >= off) ? s[t - off] : 0;
        __syncthreads();
        s[t] += x;
        __syncthreads();
    }
    if (gid < N_NODES) g_rowstart[gid] = s[t] - v;    // exclusive
    if (t == SCAN_T - 1) g_bsum[blockIdx.x] = s[t];
}

__global__ void scan_offsets() {
    if (threadIdx.x == 0 && blockIdx.x == 0) {
        int acc = 0;
        for (int i = 0; i < NBLK; i++) { int t = g_bsum[i]; g_bsum[i] = acc; acc += t; }
        g_rowstart[N_NODES] = acc;   // == N_EDGES
    }
}

__global__ void scan_add() {
    int t   = threadIdx.x;
    int gid = blockIdx.x * SCAN_T + t;
    if (gid < N_NODES) g_rowstart[gid] += g_bsum[blockIdx.x];
}

__global__ void scatter_edges(const int* __restrict__ rows, const int* __restrict__ cols) {
    int e = blockIdx.x * blockDim.x + threadIdx.x;
    if (e < N_EDGES) {
        int r   = rows[e];
        int pos = g_rowstart[r] + atomicAdd(&g_fill[r], 1);
        g_cols[pos] = cols[e];
    }
}

// ---------------- GEMM: C[n,m] = A[n,:] . B[m,:]  (both row-major, NT) ----------------
#define BM 128
#define BN 64
#define BK 16
#define TM 8
#define TN 4

__global__ __launch_bounds__(256)
void gemm_nt(const float* __restrict__ A, const float* __restrict__ B,
             const float* __restrict__ bias, float* __restrict__ C,
             int Nrows, int M, int K, int relu)
{
    __shared__ float As[BK][BM];
    __shared__ float Bs[BK][BN];

    const int tx  = threadIdx.x;          // 0..15
    const int ty  = threadIdx.y;          // 0..15
    const int tid = ty * 16 + tx;         // 0..255
    const int rowBase = blockIdx.y * BM;
    const int colBase = blockIdx.x * BN;

    float acc[TM][TN];
    #pragma unroll
    for (int i = 0; i < TM; i++)
        #pragma unroll
        for (int j = 0; j < TN; j++) acc[i][j] = 0.0f;

    for (int k0 = 0; k0 < K; k0 += BK) {
        // A tile: 128x16 = 512 float4, 2 per thread
        #pragma unroll
        for (int l = 0; l < 2; l++) {
            int idx = tid + l * 256;
            int ar  = idx >> 2;
            int kq  = (idx & 3) << 2;
            int gr  = rowBase + ar;
            float4 va = make_float4(0.f, 0.f, 0.f, 0.f);
            if (gr < Nrows)
                va = *(const float4*)(A + (size_t)gr * K + k0 + kq);
            As[kq + 0][ar] = va.x; As[kq + 1][ar] = va.y;
            As[kq + 2][ar] = va.z; As[kq + 3][ar] = va.w;
        }
        // B tile: 64x16 = 256 float4, 1 per thread
        {
            int br = tid >> 2;
            int kq = (tid & 3) << 2;
            int gm = colBase + br;
            float4 vb = make_float4(0.f, 0.f, 0.f, 0.f);
            if (gm < M)
                vb = *(const float4*)(B + (size_t)gm * K + k0 + kq);
            Bs[kq + 0][br] = vb.x; Bs[kq + 1][br] = vb.y;
            Bs[kq + 2][br] = vb.z; Bs[kq + 3][br] = vb.w;
        }
        __syncthreads();

        #pragma unroll
        for (int k = 0; k < BK; k++) {
            float a[TM], b[TN];
            #pragma unroll
            for (int i = 0; i < TM; i++) a[i] = As[k][ty * TM + i];
            #pragma unroll
            for (int j = 0; j < TN; j++) b[j] = Bs[k][tx * TN + j];
            #pragma unroll
            for (int i = 0; i < TM; i++)
                #pragma unroll
                for (int j = 0; j < TN; j++)
                    acc[i][j] += a[i] * b[j];
        }
        __syncthreads();
    }

    // epilogue: bias + optional relu, vectorized stores (M % 4 == 0)
    const int gm = colBase + tx * TN;
    if (gm < M) {
        float4 bb = *(const float4*)(bias + gm);
        #pragma unroll
        for (int i = 0; i < TM; i++) {
            int gr = rowBase + ty * TM + i;
            if (gr < Nrows) {
                float4 o;
                o.x = acc[i][0] + bb.x; o.y = acc[i][1] + bb.y;
                o.z = acc[i][2] + bb.z; o.w = acc[i][3] + bb.w;
                if (relu) {
                    o.x = fmaxf(o.x, 0.f); o.y = fmaxf(o.y, 0.f);
                    o.z = fmaxf(o.z, 0.f); o.w = fmaxf(o.w, 0.f);
                }
                *(float4*)(C + (size_t)gr * M + gm) = o;
            }
        }
    }
}

// ---------------- SpMM power-iteration step ----------------
// out[r] = 0.5*dinv[r]*(sum_{edges r->c} v[c] + v[r]) + 0.5*h[r]
__global__ __launch_bounds__(320)
void spmm_step(const float4* __restrict__ v4, const float4* __restrict__ h4,
               float4* __restrict__ out4)
{
    int t = blockIdx.x * 320 + threadIdx.x;
    int r = t / NF4;
    int f = t - r * NF4;
    if (r >= N_NODES) return;

    int s = g_rowstart[r];
    int e = g_rowstart[r + 1];

    float ax = 0.f, ay = 0.f, az = 0.f, aw = 0.f;
    int i = s;
    for (; i + 4 <= e; i += 4) {
        int c0 = g_cols[i + 0], c1 = g_cols[i + 1];
        int c2 = g_cols[i + 2], c3 = g_cols[i + 3];
        float4 p0 = __ldg(v4 + (size_t)c0 * NF4 + f);
        float4 p1 = __ldg(v4 + (size_t)c1 * NF4 + f);
        float4 p2 = __ldg(v4 + (size_t)c2 * NF4 + f);
        float4 p3 = __ldg(v4 + (size_t)c3 * NF4 + f);
        ax += (p0.x + p1.x) + (p2.x + p3.x);
        ay += (p0.y + p1.y) + (p2.y + p3.y);
        az += (p0.z + p1.z) + (p2.z + p3.z);
        aw += (p0.w + p1.w) + (p2.w + p3.w);
    }
    for (; i < e; i++) {
        int c = g_cols[i];
        float4 p = __ldg(v4 + (size_t)c * NF4 + f);
        ax += p.x; ay += p.y; az += p.z; aw += p.w;
    }

    float4 vr = __ldg(v4 + (size_t)r * NF4 + f);
    float4 hr = __ldg(h4 + (size_t)r * NF4 + f);
    float  w  = 0.5f * g_dinv[r];   // c1 = alpha/(1+alpha) = 0.5

    float4 o;
    o.x = w * (ax + vr.x) + 0.5f * hr.x;
    o.y = w * (ay + vr.y) + 0.5f * hr.y;
    o.z = w * (az + vr.z) + 0.5f * hr.z;
    o.w = w * (aw + vr.w) + 0.5f * hr.w;
    out4[(size_t)r * NF4 + f] = o;
}

// ---------------- host ----------------
extern "C" void kernel_launch(void* const* d_in, const int* in_sizes, int n_in,
                              void* d_out, int out_size)
{
    const float* x  = (const float*)d_in[0];
    const int*   ei = (const int*)  d_in[1];
    const float* W1 = (const float*)d_in[2];
    const float* b1 = (const float*)d_in[3];
    const float* W2 = (const float*)d_in[4];
    const float* b2 = (const float*)d_in[5];
    const float* W3 = (const float*)d_in[6];
    const float* b3 = (const float*)d_in[7];
    float* out = (float*)d_out;

    const int* rows = ei;            // edge_index[0]
    const int* cols = ei + N_EDGES;  // edge_index[1]

    void *p;
    float *h1, *h2, *h, *vA, *vB;
    cudaGetSymbolAddress(&p, g_h1); h1 = (float*)p;
    cudaGetSymbolAddress(&p, g_h2); h2 = (float*)p;
    cudaGetSymbolAddress(&p, g_h);  h  = (float*)p;
    cudaGetSymbolAddress(&p, g_vA); vA = (float*)p;
    cudaGetSymbolAddress(&p, g_vB); vB = (float*)p;

    // ---- CSR build ----
    zero_counts <<<(N_NODES + 255) / 256, 256>>>();
    count_deg   <<<(N_EDGES + 255) / 256, 256>>>(rows);
    compute_dinv<<<(N_NODES + 255) / 256, 256>>>();
    scan_blocks <<<NBLK, SCAN_T>>>();
    scan_offsets<<<1, 32>>>();
    scan_add    <<<NBLK, SCAN_T>>>();
    scatter_edges<<<(N_EDGES + 255) / 256, 256>>>(rows, cols);

    // ---- MLP ----
    dim3 blk(16, 16);
    dim3 g1((NHID  + BN - 1) / BN, (N_NODES + BM - 1) / BM);
    dim3 g3((NCLASS + BN - 1) / BN, (N_NODES + BM - 1) / BM);
    gemm_nt<<<g1, blk>>>(x,  W1, b1, h1, N_NODES, NHID,   NFEAT, 1);
    gemm_nt<<<g1, blk>>>(h1, W2, b2, h2, N_NODES, NHID,   NHID,  1);
    gemm_nt<<<g3, blk>>>(h2, W3, b3, h,  N_NODES, NCLASS, NHID,  0);

    // ---- 10 power iterations, ping-pong, last writes d_out ----
    const int SP_G = (N_NODES * NF4 + 319) / 320;
    const float* src = h;
    for (int it = 0; it < 10; it++) {
        float* dst = (it == 9) ? out : ((it & 1) ? vB : vA);
        spmm_step<<<SP_G, 320>>>((const float4*)src, (const float4*)h, (float4*)dst);
        src = dst;
    }
}